// round 9
// baseline (speedup 1.0000x reference)
#include <cuda_runtime.h>
#include <math.h>
#include <stdint.h>

#define BB 16
#define CC 512
#define TT 1024
#define NH 8
#define HD 64
#define NG 32
#define CPG 16

// Scratch (__device__ globals per allocation rules)
__device__ float g_xnt[BB * TT * CC];          // xn, t-major  [b][t][c]
__device__ float g_qkv[BB * 3 * CC * TT];      // [b][o][t]
__device__ float g_att[BB * TT * CC];          // h_attn, t-major [b][t][c]
__device__ float g_mean[BB * NG];
__device__ float g_inv[BB * NG];

__device__ __forceinline__ float f2tf32(float x) {
    float r;
    asm("cvt.rna.tf32.f32 %0, %1;" : "=f"(r) : "f"(x));
    return r;
}

__device__ __forceinline__ uint32_t smem_u32(const void* p) {
    uint32_t a;
    asm("{ .reg .u64 t; cvta.to.shared.u64 t, %1; cvt.u32.u64 %0, t; }"
        : "=r"(a) : "l"(p));
    return a;
}

__device__ __forceinline__ void cp16(uint32_t sdst, const void* gsrc) {
    asm volatile("cp.async.ca.shared.global [%0], [%1], 16;"
                 :: "r"(sdst), "l"(gsrc));
}
#define CP_COMMIT() asm volatile("cp.async.commit_group;" ::: "memory")
#define CP_WAIT0()  asm volatile("cp.async.wait_group 0;" ::: "memory")

__device__ __forceinline__ void mma_tf32_16x8x8(float* c, const uint32_t* a,
                                                uint32_t b0, uint32_t b1) {
    asm volatile(
        "mma.sync.aligned.m16n8k8.row.col.f32.tf32.tf32.f32 "
        "{%0,%1,%2,%3}, {%4,%5,%6,%7}, {%8,%9}, {%0,%1,%2,%3};"
        : "+f"(c[0]), "+f"(c[1]), "+f"(c[2]), "+f"(c[3])
        : "r"(a[0]), "r"(a[1]), "r"(a[2]), "r"(a[3]), "r"(b0), "r"(b1));
}

// ===========================================================================
// GroupNorm stats: one block per (b,g) -> mean, inv
// ===========================================================================
__global__ void gn_stats(const float* __restrict__ x) {
    int b = blockIdx.x >> 5;
    int g = blockIdx.x & 31;
    const float* xb = x + ((size_t)b * CC + (size_t)g * CPG) * TT;
    int tid = threadIdx.x;

    float s = 0.f, ss = 0.f;
    for (int i = tid; i < CPG * TT; i += 256) {
        float v = xb[i];
        s += v; ss += v * v;
    }
    __shared__ float rs[8], rss[8];
    #pragma unroll
    for (int o = 16; o > 0; o >>= 1) {
        s  += __shfl_down_sync(0xffffffff, s, o);
        ss += __shfl_down_sync(0xffffffff, ss, o);
    }
    if ((tid & 31) == 0) { rs[tid >> 5] = s; rss[tid >> 5] = ss; }
    __syncthreads();
    if (tid == 0) {
        float S = 0.f, SS = 0.f;
        #pragma unroll
        for (int i = 0; i < 8; i++) { S += rs[i]; SS += rss[i]; }
        float mean = S * (1.f / (CPG * TT));
        float var = SS * (1.f / (CPG * TT)) - mean * mean;
        g_mean[b * NG + g] = mean;
        g_inv[b * NG + g] = rsqrtf(var + 1e-5f);
    }
}

// ===========================================================================
// GroupNorm apply + transpose: read x[c][t] coalesced, write g_xnt[t][c].
// Scattered 4B writes merge into full sectors in L2 (neighbor warps cover
// adjacent channels of the same t rows).
// ===========================================================================
__global__ void gn_apply(const float* __restrict__ x,
                         const float* __restrict__ gamma,
                         const float* __restrict__ beta) {
    int t0 = blockIdx.x * 32;
    int b  = blockIdx.y;
    __shared__ float sa[CC], sb[CC];
    int tid = threadIdx.x;
    for (int i = tid; i < CC; i += 256) {
        int g = i >> 4;
        float mean = g_mean[b * NG + g], inv = g_inv[b * NG + g];
        float a = inv * gamma[i];
        sa[i] = a;
        sb[i] = beta[i] - mean * a;
    }
    __syncthreads();
    const float* xb = x + (size_t)b * CC * TT + t0;
    float* ob = g_xnt + ((size_t)b * TT + t0) * CC;
    #pragma unroll 4
    for (int pass = 0; pass < 16; pass++) {
        int u = pass * 256 + tid;           // 4096 float4 units: 512c x 8 t4
        int c = u >> 3, t4 = (u & 7) * 4;
        float4 v = *(const float4*)&xb[(size_t)c * TT + t4];
        float a = sa[c], bc = sb[c];
        ob[(size_t)(t4 + 0) * CC + c] = v.x * a + bc;
        ob[(size_t)(t4 + 1) * CC + c] = v.y * a + bc;
        ob[(size_t)(t4 + 2) * CC + c] = v.z * a + bc;
        ob[(size_t)(t4 + 3) * CC + c] = v.w * a + bc;
    }
}

// ===========================================================================
// tf32 mma.sync GEMM with cp.async double-buffering (verified round 8).
// ===========================================================================
#define GP 36
#define GEMM_SMEM (4 * 128 * GP * 4)   // As[2]+Bs[2]

__global__ __launch_bounds__(256) void mma_gemm(
        const float* __restrict__ Am,    // [b][T][K] t-major
        const float* __restrict__ W,     // [Mout][K]
        const float* __restrict__ bias,  // [Mout]
        const float* __restrict__ resid, // [b][Mout][T] or null
        float* __restrict__ Cm,          // [b][Mout][T]
        int Mout) {
    extern __shared__ float smg[];
    float* As = smg;                    // [2][128][GP]
    float* Bs = smg + 2 * 128 * GP;     // [2][128][GP]
    uint32_t sa = smem_u32(As), sb2 = smem_u32(Bs);

    int tid = threadIdx.x;
    int wid = tid >> 5, lane = tid & 31;
    int qm = lane >> 2, qk = lane & 3;
    int wm = wid & 3;
    int wn = wid >> 2;

    int t0 = blockIdx.x * 128, o0 = blockIdx.y * 128, b = blockIdx.z;
    const float* Ab = Am + ((size_t)b * TT + t0) * CC;
    const float* Wb = W + (size_t)o0 * CC;

    int lrow = tid >> 3, lc4 = (tid & 7) * 4;

    float acc[2][8][4];
    #pragma unroll
    for (int mt = 0; mt < 2; mt++)
        #pragma unroll
        for (int nt = 0; nt < 8; nt++)
            #pragma unroll
            for (int r = 0; r < 4; r++) acc[mt][nt][r] = 0.f;

    #define G_LOAD(kt, buf) do {                                               \
        int _k0 = (kt) * 32;                                                   \
        uint32_t _ab = sa + (uint32_t)(buf) * 128 * GP * 4;                    \
        uint32_t _bb = sb2 + (uint32_t)(buf) * 128 * GP * 4;                   \
        _Pragma("unroll")                                                      \
        for (int q = 0; q < 4; q++) {                                          \
            int row = (q * 32) + lrow;                                         \
            cp16(_ab + (uint32_t)(row * GP + lc4) * 4,                         \
                 &Ab[(size_t)row * CC + _k0 + lc4]);                           \
            cp16(_bb + (uint32_t)(row * GP + lc4) * 4,                         \
                 &Wb[(size_t)row * CC + _k0 + lc4]);                           \
        }                                                                      \
    } while (0)

    G_LOAD(0, 0);
    CP_COMMIT();

    for (int kc = 0; kc < 16; kc++) {
        CP_WAIT0();
        __syncthreads();
        if (kc + 1 < 16) { G_LOAD(kc + 1, (kc + 1) & 1); CP_COMMIT(); }

        const float* Ac = As + (kc & 1) * 128 * GP;
        const float* Bc = Bs + (kc & 1) * 128 * GP;
        #pragma unroll
        for (int ks = 0; ks < 4; ks++) {
            int kb = ks * 8;
            uint32_t af[2][4];
            #pragma unroll
            for (int mt = 0; mt < 2; mt++) {
                int r = wm * 32 + mt * 16 + qm;
                af[mt][0] = __float_as_uint(Ac[r * GP + kb + qk]);
                af[mt][1] = __float_as_uint(Ac[(r + 8) * GP + kb + qk]);
                af[mt][2] = __float_as_uint(Ac[r * GP + kb + qk + 4]);
                af[mt][3] = __float_as_uint(Ac[(r + 8) * GP + kb + qk + 4]);
            }
            #pragma unroll
            for (int nt = 0; nt < 8; nt++) {
                int cr = wn * 64 + nt * 8 + qm;
                uint32_t b0 = __float_as_uint(Bc[cr * GP + kb + qk]);
                uint32_t b1 = __float_as_uint(Bc[cr * GP + kb + qk + 4]);
                #pragma unroll
                for (int mt = 0; mt < 2; mt++)
                    mma_tf32_16x8x8(acc[mt][nt], af[mt], b0, b1);
            }
        }
    }

    #pragma unroll
    for (int mt = 0; mt < 2; mt++) {
        int tbase = t0 + wm * 32 + mt * 16 + qm;
        #pragma unroll
        for (int nt = 0; nt < 8; nt++) {
            int obase = o0 + wn * 64 + nt * 8 + 2 * qk;
            #pragma unroll
            for (int rr = 0; rr < 4; rr++) {
                int o = obase + (rr & 1);
                int t = tbase + (rr >> 1) * 8;
                size_t idx = ((size_t)b * Mout + o) * TT + t;
                float v = acc[mt][nt][rr] + bias[o];
                if (resid) v += resid[idx];
                Cm[idx] = v;
            }
        }
    }
}

// ===========================================================================
// tf32 mma.sync flash attention, cp.async double-buffered K/V.
// Softmax in log2 domain (log2e folded into Q scale); pe rounded to tf32
// before both l-sum and Ps store so P truncation bias cancels in O/l.
// ===========================================================================
#define QT 128
#define KT 64
#define KSP 72
#define VSP 68
#define PSP 68
#define KBUF (64 * KSP)
#define VBUF (64 * VSP)
#define ATT_SMEM ((2 * KBUF + 2 * VBUF + 128 * PSP) * 4)

__global__ __launch_bounds__(256) void mma_attn() {
    extern __shared__ float sm[];
    float* Ks = sm;                          // [2][64][KSP]
    float* Vs = sm + 2 * KBUF;               // [2][64][VSP]
    float* Ps = sm + 2 * KBUF + 2 * VBUF;    // [128][PSP]
    uint32_t ks_a = smem_u32(Ks), vs_a = smem_u32(Vs);

    int qt = blockIdx.x, hh = blockIdx.y, bb = blockIdx.z;
    int i0 = qt * QT;
    const float* qb = g_qkv + ((size_t)bb * 3 * CC + (size_t)hh * HD) * TT;
    const float* kb = qb + (size_t)CC * TT;
    const float* vb = kb + (size_t)CC * TT;

    int tid = threadIdx.x, wid = tid >> 5, lane = tid & 31;
    int qm = lane >> 2, qk = lane & 3;
    int wr = wid * 16;

    int ld = tid >> 4, lj4 = (tid & 15) * 4;

    #define KV_LOAD(kt, buf) do {                                              \
        int _j0 = (kt) * KT;                                                   \
        uint32_t _ka = ks_a + (uint32_t)(buf) * KBUF * 4;                      \
        uint32_t _va = vs_a + (uint32_t)(buf) * VBUF * 4;                      \
        _Pragma("unroll")                                                      \
        for (int q = 0; q < 4; q++) {                                          \
            int d = q * 16 + ld;                                               \
            cp16(_ka + (uint32_t)(d * KSP + lj4) * 4,                          \
                 &kb[(size_t)d * TT + _j0 + lj4]);                             \
            cp16(_va + (uint32_t)(d * VSP + lj4) * 4,                          \
                 &vb[(size_t)d * TT + _j0 + lj4]);                             \
        }                                                                      \
    } while (0)

    KV_LOAD(0, 0);
    CP_COMMIT();

    // Q fragments in registers, scaled by log2(e)/sqrt(64) -> log2-domain S
    const float qscale = 0.125f * 1.44269504088896f;
    uint32_t qf[8][4];
    {
        int r1 = i0 + wr + qm;
        #pragma unroll
        for (int ks = 0; ks < 8; ks++) {
            int d0 = ks * 8 + qk;
            qf[ks][0] = __float_as_uint(f2tf32(qscale * qb[(size_t)d0 * TT + r1]));
            qf[ks][1] = __float_as_uint(f2tf32(qscale * qb[(size_t)d0 * TT + r1 + 8]));
            qf[ks][2] = __float_as_uint(f2tf32(qscale * qb[(size_t)(d0 + 4) * TT + r1]));
            qf[ks][3] = __float_as_uint(f2tf32(qscale * qb[(size_t)(d0 + 4) * TT + r1 + 8]));
        }
    }

    float oacc[8][4];
    #pragma unroll
    for (int nt = 0; nt < 8; nt++)
        #pragma unroll
        for (int r = 0; r < 4; r++) oacc[nt][r] = 0.f;
    float m1 = -INFINITY, m2 = -INFINITY, l1 = 0.f, l2 = 0.f;

    for (int kt = 0; kt < 16; kt++) {
        CP_WAIT0();
        __syncthreads();
        if (kt + 1 < 16) { KV_LOAD(kt + 1, (kt + 1) & 1); CP_COMMIT(); }

        const float* Kc = Ks + (kt & 1) * KBUF;
        const float* Vc = Vs + (kt & 1) * VBUF;

        // S = Q K^T  (log2-domain logits)
        float sacc[8][4];
        #pragma unroll
        for (int nt = 0; nt < 8; nt++)
            #pragma unroll
            for (int r = 0; r < 4; r++) sacc[nt][r] = 0.f;
        #pragma unroll
        for (int ks = 0; ks < 8; ks++) {
            #pragma unroll
            for (int nt = 0; nt < 8; nt++) {
                uint32_t b0 = __float_as_uint(Kc[(ks * 8 + qk) * KSP + nt * 8 + qm]);
                uint32_t b1 = __float_as_uint(Kc[(ks * 8 + qk + 4) * KSP + nt * 8 + qm]);
                mma_tf32_16x8x8(sacc[nt], qf[ks], b0, b1);
            }
        }

        // online softmax (base-2) in registers
        float tm1 = -INFINITY, tm2 = -INFINITY;
        #pragma unroll
        for (int nt = 0; nt < 8; nt++) {
            tm1 = fmaxf(tm1, fmaxf(sacc[nt][0], sacc[nt][1]));
            tm2 = fmaxf(tm2, fmaxf(sacc[nt][2], sacc[nt][3]));
        }
        tm1 = fmaxf(tm1, __shfl_xor_sync(0xffffffff, tm1, 1));
        tm1 = fmaxf(tm1, __shfl_xor_sync(0xffffffff, tm1, 2));
        tm2 = fmaxf(tm2, __shfl_xor_sync(0xffffffff, tm2, 1));
        tm2 = fmaxf(tm2, __shfl_xor_sync(0xffffffff, tm2, 2));
        float nm1 = fmaxf(m1, tm1), nm2 = fmaxf(m2, tm2);
        float sc1 = exp2f(m1 - nm1), sc2 = exp2f(m2 - nm2);

        float rs1 = 0.f, rs2 = 0.f;
        #pragma unroll
        for (int nt = 0; nt < 8; nt++) {
            float p0 = f2tf32(exp2f(sacc[nt][0] - nm1));
            float p1 = f2tf32(exp2f(sacc[nt][1] - nm1));
            float p2 = f2tf32(exp2f(sacc[nt][2] - nm2));
            float p3 = f2tf32(exp2f(sacc[nt][3] - nm2));
            rs1 += p0 + p1;
            rs2 += p2 + p3;
            *(float2*)&Ps[(wr + qm) * PSP + nt * 8 + 2 * qk] = make_float2(p0, p1);
            *(float2*)&Ps[(wr + qm + 8) * PSP + nt * 8 + 2 * qk] = make_float2(p2, p3);
        }
        rs1 += __shfl_xor_sync(0xffffffff, rs1, 1);
        rs1 += __shfl_xor_sync(0xffffffff, rs1, 2);
        rs2 += __shfl_xor_sync(0xffffffff, rs2, 1);
        rs2 += __shfl_xor_sync(0xffffffff, rs2, 2);
        l1 = l1 * sc1 + rs1;
        l2 = l2 * sc2 + rs2;
        m1 = nm1; m2 = nm2;

        #pragma unroll
        for (int nt = 0; nt < 8; nt++) {
            oacc[nt][0] *= sc1; oacc[nt][1] *= sc1;
            oacc[nt][2] *= sc2; oacc[nt][3] *= sc2;
        }
        __syncwarp();   // Ps rows are warp-private

        // O += P V
        #pragma unroll
        for (int ks = 0; ks < 8; ks++) {
            uint32_t af[4];
            af[0] = __float_as_uint(Ps[(wr + qm) * PSP + ks * 8 + qk]);
            af[1] = __float_as_uint(Ps[(wr + qm + 8) * PSP + ks * 8 + qk]);
            af[2] = __float_as_uint(Ps[(wr + qm) * PSP + ks * 8 + qk + 4]);
            af[3] = __float_as_uint(Ps[(wr + qm + 8) * PSP + ks * 8 + qk + 4]);
            #pragma unroll
            for (int nt = 0; nt < 8; nt++) {
                uint32_t b0 = __float_as_uint(Vc[(nt * 8 + qm) * VSP + ks * 8 + qk]);
                uint32_t b1 = __float_as_uint(Vc[(nt * 8 + qm) * VSP + ks * 8 + qk + 4]);
                mma_tf32_16x8x8(oacc[nt], af, b0, b1);
            }
        }
    }

    // epilogue: O/l -> g_att[b][t][c]
    float li1 = 1.f / l1, li2 = 1.f / l2;
    float* ob = g_att + (size_t)bb * TT * CC;
    int r1 = i0 + wr + qm, r2 = r1 + 8;
    int cb = hh * HD;
    #pragma unroll
    for (int nt = 0; nt < 8; nt++) {
        *(float2*)&ob[(size_t)r1 * CC + cb + nt * 8 + 2 * qk] =
            make_float2(oacc[nt][0] * li1, oacc[nt][1] * li1);
        *(float2*)&ob[(size_t)r2 * CC + cb + nt * 8 + 2 * qk] =
            make_float2(oacc[nt][2] * li2, oacc[nt][3] * li2);
    }
}

// ===========================================================================
extern "C" void kernel_launch(void* const* d_in, const int* in_sizes, int n_in,
                              void* d_out, int out_size) {
    const float* x      = (const float*)d_in[0];
    const float* gamma  = (const float*)d_in[1];
    const float* beta   = (const float*)d_in[2];
    const float* qkv_w  = (const float*)d_in[3];
    const float* qkv_b  = (const float*)d_in[4];
    const float* proj_w = (const float*)d_in[5];
    const float* proj_b = (const float*)d_in[6];
    float* out = (float*)d_out;

    float *xnt, *qkv, *att;
    cudaGetSymbolAddress((void**)&xnt, g_xnt);
    cudaGetSymbolAddress((void**)&qkv, g_qkv);
    cudaGetSymbolAddress((void**)&att, g_att);

    static int inited = 0;
    if (!inited) {
        cudaFuncSetAttribute(mma_gemm,
                             cudaFuncAttributeMaxDynamicSharedMemorySize,
                             GEMM_SMEM);
        cudaFuncSetAttribute(mma_attn,
                             cudaFuncAttributeMaxDynamicSharedMemorySize,
                             ATT_SMEM);
        inited = 1;
    }

    // 1. GroupNorm stats + apply/transpose -> g_xnt [b][t][c]
    gn_stats<<<BB * NG, 256>>>(x);
    gn_apply<<<dim3(TT / 32, BB), 256>>>(x, gamma, beta);

    // 2. QKV GEMM (tf32 mma.sync, cp.async): out [b][1536][t]
    mma_gemm<<<dim3(TT / 128, (3 * CC) / 128, BB), 256, GEMM_SMEM>>>(
        xnt, qkv_w, qkv_b, nullptr, qkv, 3 * CC);

    // 3. Flash attention (tf32 mma.sync, cp.async) -> g_att [b][t][c]
    mma_attn<<<dim3(TT / QT, NH, BB), 256, ATT_SMEM>>>();

    // 4. Proj GEMM (tf32 mma.sync, cp.async) + bias + residual -> d_out
    mma_gemm<<<dim3(TT / 128, CC / 128, BB), 256, GEMM_SMEM>>>(
        att, proj_w, proj_b, x, out, CC);
}

// round 13
// speedup vs baseline: 1.0304x; 1.0304x over previous
#include <cuda_runtime.h>
#include <math.h>
#include <stdint.h>

#define BB 16
#define CC 512
#define TT 1024
#define NH 8
#define HD 64
#define NG 32
#define CPG 16

// Scratch (__device__ globals per allocation rules)
__device__ float g_xnt[BB * TT * CC];          // xn, t-major  [b][t][c]
__device__ float g_qkv[BB * 3 * CC * TT];      // [b][o][t]
__device__ float g_att[BB * TT * CC];          // h_attn, t-major [b][t][c]
__device__ float g_mean[BB * NG];
__device__ float g_inv[BB * NG];

__device__ __forceinline__ float f2tf32(float x) {
    float r;
    asm("cvt.rna.tf32.f32 %0, %1;" : "=f"(r) : "f"(x));
    return r;
}

__device__ __forceinline__ uint32_t smem_u32(const void* p) {
    uint32_t a;
    asm("{ .reg .u64 t; cvta.to.shared.u64 t, %1; cvt.u32.u64 %0, t; }"
        : "=r"(a) : "l"(p));
    return a;
}

__device__ __forceinline__ void cp16(uint32_t sdst, const void* gsrc) {
    asm volatile("cp.async.ca.shared.global [%0], [%1], 16;"
                 :: "r"(sdst), "l"(gsrc));
}
#define CP_COMMIT() asm volatile("cp.async.commit_group;" ::: "memory")
#define CP_WAIT0()  asm volatile("cp.async.wait_group 0;" ::: "memory")

__device__ __forceinline__ void mma_tf32_16x8x8(float* c, const uint32_t* a,
                                                uint32_t b0, uint32_t b1) {
    asm volatile(
        "mma.sync.aligned.m16n8k8.row.col.f32.tf32.tf32.f32 "
        "{%0,%1,%2,%3}, {%4,%5,%6,%7}, {%8,%9}, {%0,%1,%2,%3};"
        : "+f"(c[0]), "+f"(c[1]), "+f"(c[2]), "+f"(c[3])
        : "r"(a[0]), "r"(a[1]), "r"(a[2]), "r"(a[3]), "r"(b0), "r"(b1));
}

// ===========================================================================
// GroupNorm stats: one block per (b,g) -> mean, inv
// ===========================================================================
__global__ void gn_stats(const float* __restrict__ x) {
    int b = blockIdx.x >> 5;
    int g = blockIdx.x & 31;
    const float* xb = x + ((size_t)b * CC + (size_t)g * CPG) * TT;
    int tid = threadIdx.x;

    float s = 0.f, ss = 0.f;
    for (int i = tid; i < CPG * TT; i += 256) {
        float v = xb[i];
        s += v; ss += v * v;
    }
    __shared__ float rs[8], rss[8];
    #pragma unroll
    for (int o = 16; o > 0; o >>= 1) {
        s  += __shfl_down_sync(0xffffffff, s, o);
        ss += __shfl_down_sync(0xffffffff, ss, o);
    }
    if ((tid & 31) == 0) { rs[tid >> 5] = s; rss[tid >> 5] = ss; }
    __syncthreads();
    if (tid == 0) {
        float S = 0.f, SS = 0.f;
        #pragma unroll
        for (int i = 0; i < 8; i++) { S += rs[i]; SS += rss[i]; }
        float mean = S * (1.f / (CPG * TT));
        float var = SS * (1.f / (CPG * TT)) - mean * mean;
        g_mean[b * NG + g] = mean;
        g_inv[b * NG + g] = rsqrtf(var + 1e-5f);
    }
}

// ===========================================================================
// GroupNorm apply + transpose via smem tile (32t x 128c per block):
// coalesced float4 reads of x[c][t], smem transpose, coalesced float4
// writes of g_xnt[t][c].
// ===========================================================================
__global__ __launch_bounds__(256) void gn_apply(const float* __restrict__ x,
                                                const float* __restrict__ gamma,
                                                const float* __restrict__ beta) {
    int t0 = blockIdx.x * 32;
    int c0 = blockIdx.y * 128;
    int b  = blockIdx.z;
    __shared__ float tile[32][132];
    __shared__ float sa[128], sb[128];
    int tid = threadIdx.x;

    if (tid < 128) {
        int c = c0 + tid;
        int g = c >> 4;
        float mean = g_mean[b * NG + g], inv = g_inv[b * NG + g];
        float a = inv * gamma[c];
        sa[tid] = a;
        sb[tid] = beta[c] - mean * a;
    }
    __syncthreads();

    // read: 128 c-rows x 32 t (float4 along t), apply norm, store transposed
    const float* xb = x + (size_t)b * CC * TT + t0;
    #pragma unroll
    for (int p = 0; p < 4; p++) {
        int u = p * 256 + tid;          // 1024 units
        int cl = u >> 3;                // 0..127
        int t4 = (u & 7) * 4;           // 0..28
        float4 v = *(const float4*)&xb[(size_t)(c0 + cl) * TT + t4];
        float a = sa[cl], bc = sb[cl];
        tile[t4 + 0][cl] = v.x * a + bc;
        tile[t4 + 1][cl] = v.y * a + bc;
        tile[t4 + 2][cl] = v.z * a + bc;
        tile[t4 + 3][cl] = v.w * a + bc;
    }
    __syncthreads();

    // write: 32 t-rows x 128 c, float4 along c (conflict-free LDS.128,
    // 512B-coalesced STG.128)
    float* ob = g_xnt + ((size_t)b * TT + t0) * CC + c0;
    #pragma unroll
    for (int p = 0; p < 4; p++) {
        int u = p * 256 + tid;
        int tl = u >> 5;                // 0..31
        int c4 = (u & 31) * 4;          // 0..124
        float4 v = *(float4*)&tile[tl][c4];
        *(float4*)&ob[(size_t)tl * CC + c4] = v;
    }
}

// ===========================================================================
// tf32 mma.sync GEMM with cp.async double-buffering (verified round 8).
// ===========================================================================
#define GP 36
#define GEMM_SMEM (4 * 128 * GP * 4)   // As[2]+Bs[2]

__global__ __launch_bounds__(256) void mma_gemm(
        const float* __restrict__ Am,    // [b][T][K] t-major
        const float* __restrict__ W,     // [Mout][K]
        const float* __restrict__ bias,  // [Mout]
        const float* __restrict__ resid, // [b][Mout][T] or null
        float* __restrict__ Cm,          // [b][Mout][T]
        int Mout) {
    extern __shared__ float smg[];
    float* As = smg;                    // [2][128][GP]
    float* Bs = smg + 2 * 128 * GP;     // [2][128][GP]
    uint32_t sa = smem_u32(As), sb2 = smem_u32(Bs);

    int tid = threadIdx.x;
    int wid = tid >> 5, lane = tid & 31;
    int qm = lane >> 2, qk = lane & 3;
    int wm = wid & 3;
    int wn = wid >> 2;

    int t0 = blockIdx.x * 128, o0 = blockIdx.y * 128, b = blockIdx.z;
    const float* Ab = Am + ((size_t)b * TT + t0) * CC;
    const float* Wb = W + (size_t)o0 * CC;

    int lrow = tid >> 3, lc4 = (tid & 7) * 4;

    float acc[2][8][4];
    #pragma unroll
    for (int mt = 0; mt < 2; mt++)
        #pragma unroll
        for (int nt = 0; nt < 8; nt++)
            #pragma unroll
            for (int r = 0; r < 4; r++) acc[mt][nt][r] = 0.f;

    #define G_LOAD(kt, buf) do {                                               \
        int _k0 = (kt) * 32;                                                   \
        uint32_t _ab = sa + (uint32_t)(buf) * 128 * GP * 4;                    \
        uint32_t _bb = sb2 + (uint32_t)(buf) * 128 * GP * 4;                   \
        _Pragma("unroll")                                                      \
        for (int q = 0; q < 4; q++) {                                          \
            int row = (q * 32) + lrow;                                         \
            cp16(_ab + (uint32_t)(row * GP + lc4) * 4,                         \
                 &Ab[(size_t)row * CC + _k0 + lc4]);                           \
            cp16(_bb + (uint32_t)(row * GP + lc4) * 4,                         \
                 &Wb[(size_t)row * CC + _k0 + lc4]);                           \
        }                                                                      \
    } while (0)

    G_LOAD(0, 0);
    CP_COMMIT();

    for (int kc = 0; kc < 16; kc++) {
        CP_WAIT0();
        __syncthreads();
        if (kc + 1 < 16) { G_LOAD(kc + 1, (kc + 1) & 1); CP_COMMIT(); }

        const float* Ac = As + (kc & 1) * 128 * GP;
        const float* Bc = Bs + (kc & 1) * 128 * GP;
        #pragma unroll
        for (int ks = 0; ks < 4; ks++) {
            int kb = ks * 8;
            uint32_t af[2][4];
            #pragma unroll
            for (int mt = 0; mt < 2; mt++) {
                int r = wm * 32 + mt * 16 + qm;
                af[mt][0] = __float_as_uint(Ac[r * GP + kb + qk]);
                af[mt][1] = __float_as_uint(Ac[(r + 8) * GP + kb + qk]);
                af[mt][2] = __float_as_uint(Ac[r * GP + kb + qk + 4]);
                af[mt][3] = __float_as_uint(Ac[(r + 8) * GP + kb + qk + 4]);
            }
            #pragma unroll
            for (int nt = 0; nt < 8; nt++) {
                int cr = wn * 64 + nt * 8 + qm;
                uint32_t b0 = __float_as_uint(Bc[cr * GP + kb + qk]);
                uint32_t b1 = __float_as_uint(Bc[cr * GP + kb + qk + 4]);
                #pragma unroll
                for (int mt = 0; mt < 2; mt++)
                    mma_tf32_16x8x8(acc[mt][nt], af[mt], b0, b1);
            }
        }
    }

    #pragma unroll
    for (int mt = 0; mt < 2; mt++) {
        int tbase = t0 + wm * 32 + mt * 16 + qm;
        #pragma unroll
        for (int nt = 0; nt < 8; nt++) {
            int obase = o0 + wn * 64 + nt * 8 + 2 * qk;
            #pragma unroll
            for (int rr = 0; rr < 4; rr++) {
                int o = obase + (rr & 1);
                int t = tbase + (rr >> 1) * 8;
                size_t idx = ((size_t)b * Mout + o) * TT + t;
                float v = acc[mt][nt][rr] + bias[o];
                if (resid) v += resid[idx];
                Cm[idx] = v;
            }
        }
    }
}

// ===========================================================================
// tf32 mma.sync flash attention, cp.async double-buffered K/V,
// log2-domain online softmax in registers.
// ===========================================================================
#define QT 128
#define KT 64
#define KSP 72
#define VSP 68
#define PSP 68
#define KBUF (64 * KSP)
#define VBUF (64 * VSP)
#define ATT_SMEM ((2 * KBUF + 2 * VBUF + 128 * PSP) * 4)

__global__ __launch_bounds__(256) void mma_attn() {
    extern __shared__ float sm[];
    float* Ks = sm;                          // [2][64][KSP]
    float* Vs = sm + 2 * KBUF;               // [2][64][VSP]
    float* Ps = sm + 2 * KBUF + 2 * VBUF;    // [128][PSP]
    uint32_t ks_a = smem_u32(Ks), vs_a = smem_u32(Vs);

    int qt = blockIdx.x, hh = blockIdx.y, bb = blockIdx.z;
    int i0 = qt * QT;
    const float* qb = g_qkv + ((size_t)bb * 3 * CC + (size_t)hh * HD) * TT;
    const float* kb = qb + (size_t)CC * TT;
    const float* vb = kb + (size_t)CC * TT;

    int tid = threadIdx.x, wid = tid >> 5, lane = tid & 31;
    int qm = lane >> 2, qk = lane & 3;
    int wr = wid * 16;

    int ld = tid >> 4, lj4 = (tid & 15) * 4;

    #define KV_LOAD(kt, buf) do {                                              \
        int _j0 = (kt) * KT;                                                   \
        uint32_t _ka = ks_a + (uint32_t)(buf) * KBUF * 4;                      \
        uint32_t _va = vs_a + (uint32_t)(buf) * VBUF * 4;                      \
        _Pragma("unroll")                                                      \
        for (int q = 0; q < 4; q++) {                                          \
            int d = q * 16 + ld;                                               \
            cp16(_ka + (uint32_t)(d * KSP + lj4) * 4,                          \
                 &kb[(size_t)d * TT + _j0 + lj4]);                             \
            cp16(_va + (uint32_t)(d * VSP + lj4) * 4,                          \
                 &vb[(size_t)d * TT + _j0 + lj4]);                             \
        }                                                                      \
    } while (0)

    KV_LOAD(0, 0);
    CP_COMMIT();

    // Q fragments in registers, scaled by log2(e)/sqrt(64) -> log2-domain S
    const float qscale = 0.125f * 1.44269504088896f;
    uint32_t qf[8][4];
    {
        int r1 = i0 + wr + qm;
        #pragma unroll
        for (int ks = 0; ks < 8; ks++) {
            int d0 = ks * 8 + qk;
            qf[ks][0] = __float_as_uint(f2tf32(qscale * qb[(size_t)d0 * TT + r1]));
            qf[ks][1] = __float_as_uint(f2tf32(qscale * qb[(size_t)d0 * TT + r1 + 8]));
            qf[ks][2] = __float_as_uint(f2tf32(qscale * qb[(size_t)(d0 + 4) * TT + r1]));
            qf[ks][3] = __float_as_uint(f2tf32(qscale * qb[(size_t)(d0 + 4) * TT + r1 + 8]));
        }
    }

    float oacc[8][4];
    #pragma unroll
    for (int nt = 0; nt < 8; nt++)
        #pragma unroll
        for (int r = 0; r < 4; r++) oacc[nt][r] = 0.f;
    float m1 = -INFINITY, m2 = -INFINITY, l1 = 0.f, l2 = 0.f;

    for (int kt = 0; kt < 16; kt++) {
        CP_WAIT0();
        __syncthreads();
        if (kt + 1 < 16) { KV_LOAD(kt + 1, (kt + 1) & 1); CP_COMMIT(); }

        const float* Kc = Ks + (kt & 1) * KBUF;
        const float* Vc = Vs + (kt & 1) * VBUF;

        // S = Q K^T  (log2-domain logits)
        float sacc[8][4];
        #pragma unroll
        for (int nt = 0; nt < 8; nt++)
            #pragma unroll
            for (int r = 0; r < 4; r++) sacc[nt][r] = 0.f;
        #pragma unroll
        for (int ks = 0; ks < 8; ks++) {
            #pragma unroll
            for (int nt = 0; nt < 8; nt++) {
                uint32_t b0 = __float_as_uint(Kc[(ks * 8 + qk) * KSP + nt * 8 + qm]);
                uint32_t b1 = __float_as_uint(Kc[(ks * 8 + qk + 4) * KSP + nt * 8 + qm]);
                mma_tf32_16x8x8(sacc[nt], qf[ks], b0, b1);
            }
        }

        // online softmax (base-2) in registers
        float tm1 = -INFINITY, tm2 = -INFINITY;
        #pragma unroll
        for (int nt = 0; nt < 8; nt++) {
            tm1 = fmaxf(tm1, fmaxf(sacc[nt][0], sacc[nt][1]));
            tm2 = fmaxf(tm2, fmaxf(sacc[nt][2], sacc[nt][3]));
        }
        tm1 = fmaxf(tm1, __shfl_xor_sync(0xffffffff, tm1, 1));
        tm1 = fmaxf(tm1, __shfl_xor_sync(0xffffffff, tm1, 2));
        tm2 = fmaxf(tm2, __shfl_xor_sync(0xffffffff, tm2, 1));
        tm2 = fmaxf(tm2, __shfl_xor_sync(0xffffffff, tm2, 2));
        float nm1 = fmaxf(m1, tm1), nm2 = fmaxf(m2, tm2);
        float sc1 = exp2f(m1 - nm1), sc2 = exp2f(m2 - nm2);

        float rs1 = 0.f, rs2 = 0.f;
        #pragma unroll
        for (int nt = 0; nt < 8; nt++) {
            float p0 = exp2f(sacc[nt][0] - nm1);
            float p1 = exp2f(sacc[nt][1] - nm1);
            float p2 = exp2f(sacc[nt][2] - nm2);
            float p3 = exp2f(sacc[nt][3] - nm2);
            rs1 += p0 + p1;
            rs2 += p2 + p3;
            *(float2*)&Ps[(wr + qm) * PSP + nt * 8 + 2 * qk] = make_float2(p0, p1);
            *(float2*)&Ps[(wr + qm + 8) * PSP + nt * 8 + 2 * qk] = make_float2(p2, p3);
        }
        rs1 += __shfl_xor_sync(0xffffffff, rs1, 1);
        rs1 += __shfl_xor_sync(0xffffffff, rs1, 2);
        rs2 += __shfl_xor_sync(0xffffffff, rs2, 1);
        rs2 += __shfl_xor_sync(0xffffffff, rs2, 2);
        l1 = l1 * sc1 + rs1;
        l2 = l2 * sc2 + rs2;
        m1 = nm1; m2 = nm2;

        #pragma unroll
        for (int nt = 0; nt < 8; nt++) {
            oacc[nt][0] *= sc1; oacc[nt][1] *= sc1;
            oacc[nt][2] *= sc2; oacc[nt][3] *= sc2;
        }
        __syncwarp();   // Ps rows are warp-private

        // O += P V
        #pragma unroll
        for (int ks = 0; ks < 8; ks++) {
            uint32_t af[4];
            af[0] = __float_as_uint(Ps[(wr + qm) * PSP + ks * 8 + qk]);
            af[1] = __float_as_uint(Ps[(wr + qm + 8) * PSP + ks * 8 + qk]);
            af[2] = __float_as_uint(Ps[(wr + qm) * PSP + ks * 8 + qk + 4]);
            af[3] = __float_as_uint(Ps[(wr + qm + 8) * PSP + ks * 8 + qk + 4]);
            #pragma unroll
            for (int nt = 0; nt < 8; nt++) {
                uint32_t b0 = __float_as_uint(Vc[(nt * 8 + qm) * VSP + ks * 8 + qk]);
                uint32_t b1 = __float_as_uint(Vc[(nt * 8 + qm) * VSP + ks * 8 + qk + 4]);
                mma_tf32_16x8x8(oacc[nt], af, b0, b1);
            }
        }
    }

    // epilogue: O/l -> g_att[b][t][c]
    float li1 = 1.f / l1, li2 = 1.f / l2;
    float* ob = g_att + (size_t)bb * TT * CC;
    int r1 = i0 + wr + qm, r2 = r1 + 8;
    int cb = hh * HD;
    #pragma unroll
    for (int nt = 0; nt < 8; nt++) {
        *(float2*)&ob[(size_t)r1 * CC + cb + nt * 8 + 2 * qk] =
            make_float2(oacc[nt][0] * li1, oacc[nt][1] * li1);
        *(float2*)&ob[(size_t)r2 * CC + cb + nt * 8 + 2 * qk] =
            make_float2(oacc[nt][2] * li2, oacc[nt][3] * li2);
    }
}

// ===========================================================================
extern "C" void kernel_launch(void* const* d_in, const int* in_sizes, int n_in,
                              void* d_out, int out_size) {
    const float* x      = (const float*)d_in[0];
    const float* gamma  = (const float*)d_in[1];
    const float* beta   = (const float*)d_in[2];
    const float* qkv_w  = (const float*)d_in[3];
    const float* qkv_b  = (const float*)d_in[4];
    const float* proj_w = (const float*)d_in[5];
    const float* proj_b = (const float*)d_in[6];
    float* out = (float*)d_out;

    float *xnt, *qkv, *att;
    cudaGetSymbolAddress((void**)&xnt, g_xnt);
    cudaGetSymbolAddress((void**)&qkv, g_qkv);
    cudaGetSymbolAddress((void**)&att, g_att);

    static int inited = 0;
    if (!inited) {
        cudaFuncSetAttribute(mma_gemm,
                             cudaFuncAttributeMaxDynamicSharedMemorySize,
                             GEMM_SMEM);
        cudaFuncSetAttribute(mma_attn,
                             cudaFuncAttributeMaxDynamicSharedMemorySize,
                             ATT_SMEM);
        inited = 1;
    }

    // 1. GroupNorm stats + tiled-transpose apply -> g_xnt [b][t][c]
    gn_stats<<<BB * NG, 256>>>(x);
    gn_apply<<<dim3(TT / 32, CC / 128, BB), 256>>>(x, gamma, beta);

    // 2. QKV GEMM (tf32 mma.sync, cp.async): out [b][1536][t]
    mma_gemm<<<dim3(TT / 128, (3 * CC) / 128, BB), 256, GEMM_SMEM>>>(
        xnt, qkv_w, qkv_b, nullptr, qkv, 3 * CC);

    // 3. Flash attention (tf32 mma.sync, cp.async) -> g_att [b][t][c]
    mma_attn<<<dim3(TT / QT, NH, BB), 256, ATT_SMEM>>>();

    // 4. Proj GEMM (tf32 mma.sync, cp.async) + bias + residual -> d_out
    mma_gemm<<<dim3(TT / 128, CC / 128, BB), 256, GEMM_SMEM>>>(
        att, proj_w, proj_b, x, out, CC);
}

// round 15
// speedup vs baseline: 1.2647x; 1.2275x over previous
#include <cuda_runtime.h>
#include <cuda_bf16.h>
#include <math.h>
#include <stdint.h>

#define BB 16
#define CC 512
#define TT 1024
#define NH 8
#define HD 64
#define NG 32
#define CPG 16

// Scratch (__device__ globals per allocation rules)
__device__ float g_xnt[BB * TT * CC];            // xn, t-major [b][t][c]
__device__ float g_qkv[BB * 3 * CC * TT];        // [b][o][t] (V region unused)
__device__ __nv_bfloat16 g_vb[BB * CC * TT];     // V bf16 [b][c][t]
__device__ float g_att[BB * TT * CC];            // h_attn, t-major [b][t][c]
__device__ float g_mean[BB * NG];
__device__ float g_inv[BB * NG];

__device__ __forceinline__ float f2tf32(float x) {
    float r;
    asm("cvt.rna.tf32.f32 %0, %1;" : "=f"(r) : "f"(x));
    return r;
}

__device__ __forceinline__ uint32_t pkbf(float lo, float hi) {
    uint32_t r;
    asm("cvt.rn.bf16x2.f32 %0, %1, %2;" : "=r"(r) : "f"(hi), "f"(lo));
    return r;
}

__device__ __forceinline__ uint32_t smem_u32(const void* p) {
    uint32_t a;
    asm("{ .reg .u64 t; cvta.to.shared.u64 t, %1; cvt.u32.u64 %0, t; }"
        : "=r"(a) : "l"(p));
    return a;
}

__device__ __forceinline__ void cp16(uint32_t sdst, const void* gsrc) {
    asm volatile("cp.async.ca.shared.global [%0], [%1], 16;"
                 :: "r"(sdst), "l"(gsrc));
}
#define CP_COMMIT() asm volatile("cp.async.commit_group;" ::: "memory")
#define CP_WAIT0()  asm volatile("cp.async.wait_group 0;" ::: "memory")

__device__ __forceinline__ void mma_tf32_16x8x8(float* c, const uint32_t* a,
                                                uint32_t b0, uint32_t b1) {
    asm volatile(
        "mma.sync.aligned.m16n8k8.row.col.f32.tf32.tf32.f32 "
        "{%0,%1,%2,%3}, {%4,%5,%6,%7}, {%8,%9}, {%0,%1,%2,%3};"
        : "+f"(c[0]), "+f"(c[1]), "+f"(c[2]), "+f"(c[3])
        : "r"(a[0]), "r"(a[1]), "r"(a[2]), "r"(a[3]), "r"(b0), "r"(b1));
}

__device__ __forceinline__ void mma_bf16_16x8x16(float* c, const uint32_t* a,
                                                 uint32_t b0, uint32_t b1) {
    asm volatile(
        "mma.sync.aligned.m16n8k16.row.col.f32.bf16.bf16.f32 "
        "{%0,%1,%2,%3}, {%4,%5,%6,%7}, {%8,%9}, {%0,%1,%2,%3};"
        : "+f"(c[0]), "+f"(c[1]), "+f"(c[2]), "+f"(c[3])
        : "r"(a[0]), "r"(a[1]), "r"(a[2]), "r"(a[3]), "r"(b0), "r"(b1));
}

// ===========================================================================
// GroupNorm stats: one block per (b,g) -> mean, inv
// ===========================================================================
__global__ void gn_stats(const float* __restrict__ x) {
    int b = blockIdx.x >> 5;
    int g = blockIdx.x & 31;
    const float* xb = x + ((size_t)b * CC + (size_t)g * CPG) * TT;
    int tid = threadIdx.x;

    float s = 0.f, ss = 0.f;
    for (int i = tid; i < CPG * TT; i += 256) {
        float v = xb[i];
        s += v; ss += v * v;
    }
    __shared__ float rs[8], rss[8];
    #pragma unroll
    for (int o = 16; o > 0; o >>= 1) {
        s  += __shfl_down_sync(0xffffffff, s, o);
        ss += __shfl_down_sync(0xffffffff, ss, o);
    }
    if ((tid & 31) == 0) { rs[tid >> 5] = s; rss[tid >> 5] = ss; }
    __syncthreads();
    if (tid == 0) {
        float S = 0.f, SS = 0.f;
        #pragma unroll
        for (int i = 0; i < 8; i++) { S += rs[i]; SS += rss[i]; }
        float mean = S * (1.f / (CPG * TT));
        float var = SS * (1.f / (CPG * TT)) - mean * mean;
        g_mean[b * NG + g] = mean;
        g_inv[b * NG + g] = rsqrtf(var + 1e-5f);
    }
}

// ===========================================================================
// GroupNorm apply + transpose via smem tile (32t x 128c per block)
// ===========================================================================
__global__ __launch_bounds__(256) void gn_apply(const float* __restrict__ x,
                                                const float* __restrict__ gamma,
                                                const float* __restrict__ beta) {
    int t0 = blockIdx.x * 32;
    int c0 = blockIdx.y * 128;
    int b  = blockIdx.z;
    __shared__ float tile[32][132];
    __shared__ float sa[128], sb[128];
    int tid = threadIdx.x;

    if (tid < 128) {
        int c = c0 + tid;
        int g = c >> 4;
        float mean = g_mean[b * NG + g], inv = g_inv[b * NG + g];
        float a = inv * gamma[c];
        sa[tid] = a;
        sb[tid] = beta[c] - mean * a;
    }
    __syncthreads();

    const float* xb = x + (size_t)b * CC * TT + t0;
    #pragma unroll
    for (int p = 0; p < 4; p++) {
        int u = p * 256 + tid;
        int cl = u >> 3;
        int t4 = (u & 7) * 4;
        float4 v = *(const float4*)&xb[(size_t)(c0 + cl) * TT + t4];
        float a = sa[cl], bc = sb[cl];
        tile[t4 + 0][cl] = v.x * a + bc;
        tile[t4 + 1][cl] = v.y * a + bc;
        tile[t4 + 2][cl] = v.z * a + bc;
        tile[t4 + 3][cl] = v.w * a + bc;
    }
    __syncthreads();

    float* ob = g_xnt + ((size_t)b * TT + t0) * CC + c0;
    #pragma unroll
    for (int p = 0; p < 4; p++) {
        int u = p * 256 + tid;
        int tl = u >> 5;
        int c4 = (u & 31) * 4;
        float4 v = *(float4*)&tile[tl][c4];
        *(float4*)&ob[(size_t)tl * CC + c4] = v;
    }
}

// ===========================================================================
// tf32 mma.sync GEMM with cp.async double-buffering.
// When vout != null, o-blocks >= 1024 (the V rows of QKV) write bf16 to vout
// instead of fp32 to Cm.
// ===========================================================================
#define GP 36
#define GEMM_SMEM (4 * 128 * GP * 4)   // As[2]+Bs[2]

__global__ __launch_bounds__(256) void mma_gemm(
        const float* __restrict__ Am,    // [b][T][K] t-major
        const float* __restrict__ W,     // [Mout][K]
        const float* __restrict__ bias,  // [Mout]
        const float* __restrict__ resid, // [b][Mout][T] or null
        float* __restrict__ Cm,          // [b][Mout][T]
        __nv_bfloat16* __restrict__ vout,// bf16 V out [b][CC][T] or null
        int Mout) {
    extern __shared__ float smg[];
    float* As = smg;
    float* Bs = smg + 2 * 128 * GP;
    uint32_t sa = smem_u32(As), sb2 = smem_u32(Bs);

    int tid = threadIdx.x;
    int wid = tid >> 5, lane = tid & 31;
    int qm = lane >> 2, qk = lane & 3;
    int wm = wid & 3;
    int wn = wid >> 2;

    int t0 = blockIdx.x * 128, o0 = blockIdx.y * 128, b = blockIdx.z;
    const float* Ab = Am + ((size_t)b * TT + t0) * CC;
    const float* Wb = W + (size_t)o0 * CC;
    bool isv = (vout != nullptr) && (o0 >= 1024);

    int lrow = tid >> 3, lc4 = (tid & 7) * 4;

    float acc[2][8][4];
    #pragma unroll
    for (int mt = 0; mt < 2; mt++)
        #pragma unroll
        for (int nt = 0; nt < 8; nt++)
            #pragma unroll
            for (int r = 0; r < 4; r++) acc[mt][nt][r] = 0.f;

    #define G_LOAD(kt, buf) do {                                               \
        int _k0 = (kt) * 32;                                                   \
        uint32_t _ab = sa + (uint32_t)(buf) * 128 * GP * 4;                    \
        uint32_t _bb = sb2 + (uint32_t)(buf) * 128 * GP * 4;                   \
        _Pragma("unroll")                                                      \
        for (int q = 0; q < 4; q++) {                                          \
            int row = (q * 32) + lrow;                                         \
            cp16(_ab + (uint32_t)(row * GP + lc4) * 4,                         \
                 &Ab[(size_t)row * CC + _k0 + lc4]);                           \
            cp16(_bb + (uint32_t)(row * GP + lc4) * 4,                         \
                 &Wb[(size_t)row * CC + _k0 + lc4]);                           \
        }                                                                      \
    } while (0)

    G_LOAD(0, 0);
    CP_COMMIT();

    for (int kc = 0; kc < 16; kc++) {
        CP_WAIT0();
        __syncthreads();
        if (kc + 1 < 16) { G_LOAD(kc + 1, (kc + 1) & 1); CP_COMMIT(); }

        const float* Ac = As + (kc & 1) * 128 * GP;
        const float* Bc = Bs + (kc & 1) * 128 * GP;
        #pragma unroll
        for (int ks = 0; ks < 4; ks++) {
            int kb = ks * 8;
            uint32_t af[2][4];
            #pragma unroll
            for (int mt = 0; mt < 2; mt++) {
                int r = wm * 32 + mt * 16 + qm;
                af[mt][0] = __float_as_uint(Ac[r * GP + kb + qk]);
                af[mt][1] = __float_as_uint(Ac[(r + 8) * GP + kb + qk]);
                af[mt][2] = __float_as_uint(Ac[r * GP + kb + qk + 4]);
                af[mt][3] = __float_as_uint(Ac[(r + 8) * GP + kb + qk + 4]);
            }
            #pragma unroll
            for (int nt = 0; nt < 8; nt++) {
                int cr = wn * 64 + nt * 8 + qm;
                uint32_t b0 = __float_as_uint(Bc[cr * GP + kb + qk]);
                uint32_t b1 = __float_as_uint(Bc[cr * GP + kb + qk + 4]);
                #pragma unroll
                for (int mt = 0; mt < 2; mt++)
                    mma_tf32_16x8x8(acc[mt][nt], af[mt], b0, b1);
            }
        }
    }

    #pragma unroll
    for (int mt = 0; mt < 2; mt++) {
        int tbase = t0 + wm * 32 + mt * 16 + qm;
        #pragma unroll
        for (int nt = 0; nt < 8; nt++) {
            int obase = o0 + wn * 64 + nt * 8 + 2 * qk;
            #pragma unroll
            for (int rr = 0; rr < 4; rr++) {
                int o = obase + (rr & 1);
                int t = tbase + (rr >> 1) * 8;
                float v = acc[mt][nt][rr] + bias[o];
                if (isv) {
                    vout[((size_t)b * CC + (o - 1024)) * TT + t] =
                        __float2bfloat16(v);
                } else {
                    size_t idx = ((size_t)b * Mout + o) * TT + t;
                    if (resid) v += resid[idx];
                    Cm[idx] = v;
                }
            }
        }
    }
}

// ===========================================================================
// Flash attention: tf32 QK^T + bf16 PV (m16n8k16), P kept in registers
// (accumulator layout == bf16 A-fragment layout), cp.async double-buffered.
// ===========================================================================
#define QT 128
#define KT 64
#define KSP 72
#define VSPB 72                       // bf16 elems per V row
#define KBUF (64 * KSP)               // floats
#define VBUFB (64 * VSPB)             // bf16 elems
#define ATT_SMEM (2 * KBUF * 4 + 2 * VBUFB * 2)

__global__ __launch_bounds__(256) void mma_attn() {
    extern __shared__ char smc[];
    float* Ks = (float*)smc;                           // [2][64][KSP] fp32
    uint16_t* Vsb = (uint16_t*)(smc + 2 * KBUF * 4);   // [2][64][VSPB] bf16
    uint32_t ks_a = smem_u32(Ks), vs_a = smem_u32(Vsb);

    int qt = blockIdx.x, hh = blockIdx.y, bb = blockIdx.z;
    int i0 = qt * QT;
    const float* qb = g_qkv + ((size_t)bb * 3 * CC + (size_t)hh * HD) * TT;
    const float* kb = qb + (size_t)CC * TT;
    const __nv_bfloat16* vbg = g_vb + ((size_t)bb * CC + (size_t)hh * HD) * TT;

    int tid = threadIdx.x, wid = tid >> 5, lane = tid & 31;
    int qm = lane >> 2, qk = lane & 3;
    int wr = wid * 16;

    int ld = tid >> 4, lj4 = (tid & 15) * 4;     // K: 16 rows x 16 j-chunks
    int vld = tid >> 3, vj8 = (tid & 7) * 8;     // V: 32 rows x 8 j-chunks

    #define KV_LOAD(kt, buf) do {                                              \
        int _j0 = (kt) * KT;                                                   \
        uint32_t _ka = ks_a + (uint32_t)(buf) * KBUF * 4;                      \
        uint32_t _va = vs_a + (uint32_t)(buf) * VBUFB * 2;                     \
        _Pragma("unroll")                                                      \
        for (int q = 0; q < 4; q++) {                                          \
            int d = q * 16 + ld;                                               \
            cp16(_ka + (uint32_t)(d * KSP + lj4) * 4,                          \
                 &kb[(size_t)d * TT + _j0 + lj4]);                             \
        }                                                                      \
        _Pragma("unroll")                                                      \
        for (int q = 0; q < 2; q++) {                                          \
            int d = q * 32 + vld;                                              \
            cp16(_va + (uint32_t)(d * VSPB + vj8) * 2,                         \
                 &vbg[(size_t)d * TT + _j0 + vj8]);                            \
        }                                                                      \
    } while (0)

    KV_LOAD(0, 0);
    CP_COMMIT();

    // Q fragments in registers, scaled by log2(e)/sqrt(64) -> log2-domain S
    const float qscale = 0.125f * 1.44269504088896f;
    uint32_t qf[8][4];
    {
        int r1 = i0 + wr + qm;
        #pragma unroll
        for (int ks = 0; ks < 8; ks++) {
            int d0 = ks * 8 + qk;
            qf[ks][0] = __float_as_uint(f2tf32(qscale * qb[(size_t)d0 * TT + r1]));
            qf[ks][1] = __float_as_uint(f2tf32(qscale * qb[(size_t)d0 * TT + r1 + 8]));
            qf[ks][2] = __float_as_uint(f2tf32(qscale * qb[(size_t)(d0 + 4) * TT + r1]));
            qf[ks][3] = __float_as_uint(f2tf32(qscale * qb[(size_t)(d0 + 4) * TT + r1 + 8]));
        }
    }

    float oacc[8][4];
    #pragma unroll
    for (int nt = 0; nt < 8; nt++)
        #pragma unroll
        for (int r = 0; r < 4; r++) oacc[nt][r] = 0.f;
    float m1 = -INFINITY, m2 = -INFINITY, l1 = 0.f, l2 = 0.f;

    for (int kt = 0; kt < 16; kt++) {
        CP_WAIT0();
        __syncthreads();
        if (kt + 1 < 16) { KV_LOAD(kt + 1, (kt + 1) & 1); CP_COMMIT(); }

        const float* Kc = Ks + (kt & 1) * KBUF;
        const uint16_t* Vc = Vsb + (kt & 1) * VBUFB;

        // S = Q K^T  (tf32, log2-domain logits)
        float sacc[8][4];
        #pragma unroll
        for (int nt = 0; nt < 8; nt++)
            #pragma unroll
            for (int r = 0; r < 4; r++) sacc[nt][r] = 0.f;
        #pragma unroll
        for (int ks = 0; ks < 8; ks++) {
            #pragma unroll
            for (int nt = 0; nt < 8; nt++) {
                uint32_t b0 = __float_as_uint(Kc[(ks * 8 + qk) * KSP + nt * 8 + qm]);
                uint32_t b1 = __float_as_uint(Kc[(ks * 8 + qk + 4) * KSP + nt * 8 + qm]);
                mma_tf32_16x8x8(sacc[nt], qf[ks], b0, b1);
            }
        }

        // online softmax (base-2) in registers; p overwrites sacc
        float tm1 = -INFINITY, tm2 = -INFINITY;
        #pragma unroll
        for (int nt = 0; nt < 8; nt++) {
            tm1 = fmaxf(tm1, fmaxf(sacc[nt][0], sacc[nt][1]));
            tm2 = fmaxf(tm2, fmaxf(sacc[nt][2], sacc[nt][3]));
        }
        tm1 = fmaxf(tm1, __shfl_xor_sync(0xffffffff, tm1, 1));
        tm1 = fmaxf(tm1, __shfl_xor_sync(0xffffffff, tm1, 2));
        tm2 = fmaxf(tm2, __shfl_xor_sync(0xffffffff, tm2, 1));
        tm2 = fmaxf(tm2, __shfl_xor_sync(0xffffffff, tm2, 2));
        float nm1 = fmaxf(m1, tm1), nm2 = fmaxf(m2, tm2);
        float sc1 = exp2f(m1 - nm1), sc2 = exp2f(m2 - nm2);

        float rs1 = 0.f, rs2 = 0.f;
        #pragma unroll
        for (int nt = 0; nt < 8; nt++) {
            float p0 = exp2f(sacc[nt][0] - nm1);
            float p1 = exp2f(sacc[nt][1] - nm1);
            float p2 = exp2f(sacc[nt][2] - nm2);
            float p3 = exp2f(sacc[nt][3] - nm2);
            rs1 += p0 + p1;
            rs2 += p2 + p3;
            sacc[nt][0] = p0; sacc[nt][1] = p1;
            sacc[nt][2] = p2; sacc[nt][3] = p3;
        }
        rs1 += __shfl_xor_sync(0xffffffff, rs1, 1);
        rs1 += __shfl_xor_sync(0xffffffff, rs1, 2);
        rs2 += __shfl_xor_sync(0xffffffff, rs2, 1);
        rs2 += __shfl_xor_sync(0xffffffff, rs2, 2);
        l1 = l1 * sc1 + rs1;
        l2 = l2 * sc2 + rs2;
        m1 = nm1; m2 = nm2;

        #pragma unroll
        for (int nt = 0; nt < 8; nt++) {
            oacc[nt][0] *= sc1; oacc[nt][1] *= sc1;
            oacc[nt][2] *= sc2; oacc[nt][3] *= sc2;
        }

        // O += P V  (bf16 m16n8k16; A-frags packed from sacc registers)
        #pragma unroll
        for (int g = 0; g < 4; g++) {
            uint32_t af[4];
            af[0] = pkbf(sacc[2 * g][0],     sacc[2 * g][1]);
            af[1] = pkbf(sacc[2 * g][2],     sacc[2 * g][3]);
            af[2] = pkbf(sacc[2 * g + 1][0], sacc[2 * g + 1][1]);
            af[3] = pkbf(sacc[2 * g + 1][2], sacc[2 * g + 1][3]);
            #pragma unroll
            for (int nt = 0; nt < 8; nt++) {
                const uint16_t* vrow = &Vc[(nt * 8 + qm) * VSPB + g * 16 + 2 * qk];
                uint32_t b0 = *(const uint32_t*)vrow;
                uint32_t b1 = *(const uint32_t*)(vrow + 8);
                mma_bf16_16x8x16(oacc[nt], af, b0, b1);
            }
        }
    }

    // epilogue: O/l -> g_att[b][t][c]
    float li1 = 1.f / l1, li2 = 1.f / l2;
    float* ob = g_att + (size_t)bb * TT * CC;
    int r1 = i0 + wr + qm, r2 = r1 + 8;
    int cb = hh * HD;
    #pragma unroll
    for (int nt = 0; nt < 8; nt++) {
        *(float2*)&ob[(size_t)r1 * CC + cb + nt * 8 + 2 * qk] =
            make_float2(oacc[nt][0] * li1, oacc[nt][1] * li1);
        *(float2*)&ob[(size_t)r2 * CC + cb + nt * 8 + 2 * qk] =
            make_float2(oacc[nt][2] * li2, oacc[nt][3] * li2);
    }
}

// ===========================================================================
extern "C" void kernel_launch(void* const* d_in, const int* in_sizes, int n_in,
                              void* d_out, int out_size) {
    const float* x      = (const float*)d_in[0];
    const float* gamma  = (const float*)d_in[1];
    const float* beta   = (const float*)d_in[2];
    const float* qkv_w  = (const float*)d_in[3];
    const float* qkv_b  = (const float*)d_in[4];
    const float* proj_w = (const float*)d_in[5];
    const float* proj_b = (const float*)d_in[6];
    float* out = (float*)d_out;

    float *xnt, *qkv, *att;
    __nv_bfloat16* vb;
    cudaGetSymbolAddress((void**)&xnt, g_xnt);
    cudaGetSymbolAddress((void**)&qkv, g_qkv);
    cudaGetSymbolAddress((void**)&att, g_att);
    cudaGetSymbolAddress((void**)&vb,  g_vb);

    static int inited = 0;
    if (!inited) {
        cudaFuncSetAttribute(mma_gemm,
                             cudaFuncAttributeMaxDynamicSharedMemorySize,
                             GEMM_SMEM);
        cudaFuncSetAttribute(mma_attn,
                             cudaFuncAttributeMaxDynamicSharedMemorySize,
                             ATT_SMEM);
        inited = 1;
    }

    // 1. GroupNorm stats + tiled-transpose apply -> g_xnt [b][t][c]
    gn_stats<<<BB * NG, 256>>>(x);
    gn_apply<<<dim3(TT / 32, CC / 128, BB), 256>>>(x, gamma, beta);

    // 2. QKV GEMM: Q,K fp32 -> g_qkv ; V bf16 -> g_vb
    mma_gemm<<<dim3(TT / 128, (3 * CC) / 128, BB), 256, GEMM_SMEM>>>(
        xnt, qkv_w, qkv_b, nullptr, qkv, vb, 3 * CC);

    // 3. Flash attention (tf32 QK + bf16 PV) -> g_att [b][t][c]
    mma_attn<<<dim3(TT / QT, NH, BB), 256, ATT_SMEM>>>();

    // 4. Proj GEMM + bias + residual -> d_out
    mma_gemm<<<dim3(TT / 128, CC / 128, BB), 256, GEMM_SMEM>>>(
        att, proj_w, proj_b, x, out, nullptr, CC);
}